// round 1
// baseline (speedup 1.0000x reference)
#include <cuda_runtime.h>
#include <math.h>

// ---------------- static scratch (device globals; no allocation) ----------------
#define LMAX 4096
__device__ float g_x    [64*LMAX];        // current feature map (64, L)
__device__ float g_h    [64*LMAX];        // ln output
__device__ float g_t1   [64*256*256];     // big temp (resize)
__device__ float g_t2   [64*128*128];     // conv temp
__device__ float g_s0   [64*4096];        // skip stage0
__device__ float g_s1   [64*1024];        // skip stage1
__device__ float g_s2   [64*256];         // skip stage2
__device__ float g_xz   [256*LMAX];       // in-proj output (xc rows 0..127, z rows 128..255)
__device__ float g_xconv[128*LMAX];       // depthwise conv + silu
__device__ float g_xs   [4*128*LMAX];     // 4-direction traversals
__device__ float g_dts  [4*4*LMAX];
__device__ float g_Bm   [4*LMAX*16];      // (k, l, n)
__device__ float g_Cm   [4*LMAX*16];      // (k, l, n)
__device__ float g_delta[4*128*LMAX];
__device__ float g_aP   [4*128*32*16];    // chunk decay
__device__ float g_hE   [4*128*32*16];    // chunk local end-state
__device__ float g_hI   [4*128*32*16];    // chunk input state
__device__ float g_ys   [4*128*LMAX];     // per-direction scan output
__device__ float g_yc   [128*LMAX];       // combined y

__device__ __forceinline__ float* bufptr(int id){
  switch(id){
    case 0: return g_x;
    case 1: return g_h;
    case 2: return g_t1;
    case 3: return g_t2;
    case 4: return g_s0;
    case 5: return g_s1;
    default: return g_s2;
  }
}

__device__ __forceinline__ float siluf(float x){ return x / (1.0f + __expf(-x)); }
__device__ __forceinline__ float softplusf(float x){ return (x > 20.0f) ? x : log1pf(__expf(x)); }

// ---------------- kernels ----------------

// patch embed: E0 (1,256,256) -> g_x (64,64,64), conv 4x4 stride 4
__global__ void k_patch_embed(const float* __restrict__ E0, const float* __restrict__ w,
                              const float* __restrict__ b){
  int idx = blockIdx.x*blockDim.x + threadIdx.x;
  if(idx >= 64*4096) return;
  int c = idx >> 12, p = idx & 4095;
  int oh = p >> 6, ow = p & 63;
  const float* wp = w + c*16;
  float acc = b[c];
  #pragma unroll
  for(int i=0;i<4;i++)
    #pragma unroll
    for(int j=0;j<4;j++)
      acc += E0[(oh*4+i)*256 + ow*4 + j] * wp[i*4+j];
  g_x[idx] = acc;
}

// layernorm over channels at each pixel (NCHW, channel-stride = L)
__global__ void k_ln2d(int inid, int outid, const float* __restrict__ g,
                       const float* __restrict__ b, int Cn, int L){
  int p = blockIdx.x*blockDim.x + threadIdx.x;
  if(p >= L) return;
  const float* in = bufptr(inid);
  float* out = bufptr(outid);
  float mu = 0.f;
  for(int c=0;c<Cn;c++) mu += in[c*L+p];
  mu /= (float)Cn;
  float var = 0.f;
  for(int c=0;c<Cn;c++){ float d = in[c*L+p]-mu; var += d*d; }
  var /= (float)Cn;
  float rs = rsqrtf(var + 1e-6f);
  for(int c=0;c<Cn;c++) out[c*L+p] = (in[c*L+p]-mu)*rs*g[c] + b[c];
}

// xz[e,p] = sum_c h[c,p] * in_w[c*256+e]   (64 -> 256)
__global__ void k_inproj(const float* __restrict__ inw, int L){
  int idx = blockIdx.x*blockDim.x + threadIdx.x;
  if(idx >= 256*L) return;
  int e = idx / L, p = idx % L;
  float acc = 0.f;
  #pragma unroll 4
  for(int c=0;c<64;c++) acc += g_h[c*L+p]*inw[c*256+e];
  g_xz[idx] = acc;
}

// depthwise 3x3 pad1 + bias + silu on xz rows 0..127 -> g_xconv
__global__ void k_dwconv_silu(const float* __restrict__ w, const float* __restrict__ b,
                              int H, int W){
  int L = H*W;
  int idx = blockIdx.x*blockDim.x + threadIdx.x;
  if(idx >= 128*L) return;
  int d = idx / L, p = idx % L;
  int hh = p / W, ww = p % W;
  const float* in = g_xz + d*L;
  const float* wp = w + d*9;
  float acc = b[d];
  #pragma unroll
  for(int i=-1;i<=1;i++){
    int ih = hh+i; if(ih<0 || ih>=H) continue;
    #pragma unroll
    for(int j=-1;j<=1;j++){
      int iw = ww+j; if(iw<0 || iw>=W) continue;
      acc += in[ih*W+iw]*wp[(i+1)*3+(j+1)];
    }
  }
  g_xconv[idx] = siluf(acc);
}

__device__ __forceinline__ int permk(int k, int l, int H, int W, int L){
  if(k==0) return l;
  if(k==1) return (l%H)*W + l/H;
  if(k==2) return L-1-l;
  int l2 = L-1-l; return (l2%H)*W + l2/H;
}

__global__ void k_build_xs(int H, int W){
  int L = H*W;
  int idx = blockIdx.x*blockDim.x + threadIdx.x;
  if(idx >= 512*L) return;
  int l = idx % L; int kd = idx / L; int d = kd & 127; int k = kd >> 7;
  g_xs[idx] = g_xconv[d*L + permk(k,l,H,W,L)];
}

// xdbl[k,r,l] = sum_d xs[k,d,l] * xp_w[(k*36+r)*128+d]; split into dts/B/C
__global__ void k_xproj(const float* __restrict__ xpw, int L){
  int idx = blockIdx.x*blockDim.x + threadIdx.x;
  if(idx >= 4*36*L) return;
  int l = idx % L; int kr = idx / L; int r = kr % 36; int k = kr / 36;
  const float* xs = g_xs + k*128*L + l;
  const float* w = xpw + (k*36+r)*128;
  float acc = 0.f;
  #pragma unroll 4
  for(int d=0;d<128;d++) acc += xs[d*L]*w[d];
  if(r < 4)       g_dts[(k*4+r)*L + l] = acc;
  else if(r < 20) g_Bm[(k*L+l)*16 + (r-4)] = acc;
  else            g_Cm[(k*L+l)*16 + (r-20)] = acc;
}

// delta[k,d,l] = softplus(sum_r dts*dt_w + dt_b)
__global__ void k_delta(const float* __restrict__ dtw, const float* __restrict__ dtb, int L){
  int idx = blockIdx.x*blockDim.x + threadIdx.x;
  if(idx >= 512*L) return;
  int l = idx % L; int kd = idx / L; int k = kd >> 7;
  const float* w = dtw + kd*4;
  float acc = dtb[kd];
  #pragma unroll
  for(int r=0;r<4;r++) acc += g_dts[(k*4+r)*L + l]*w[r];
  g_delta[idx] = softplusf(acc);
}

// scan pass 1: per (k,d,chunk,n): local scan from 0 -> hEnd; chunk decay exp(A*sum(delta))
__global__ void k_scan1(const float* __restrict__ alog, int L, int NC, int CH){
  int tid = blockIdx.x*blockDim.x + threadIdx.x;
  if(tid >= 512*NC*16) return;
  int n = tid & 15;
  int gid = tid >> 4;
  int c = gid % NC; int kd = gid / NC;
  int k = kd >> 7;
  float A = -__expf(alog[kd*16+n]);
  const float* dl = g_delta + kd*L;
  const float* us = g_xs + kd*L;
  const float* Bp = g_Bm + k*L*16 + n;
  float h = 0.f, sd = 0.f;
  int l0 = c*CH;
  for(int l=l0; l<l0+CH; l++){
    float dlt = dl[l];
    float dA = __expf(dlt*A);
    h = dA*h + dlt*Bp[l*16]*us[l];
    sd += dlt;
  }
  int aidx = (kd*NC + c)*16 + n;
  g_aP[aidx] = __expf(A*sd);
  g_hE[aidx] = h;
}

// scan pass 2: sequential over chunks: hIn[c] = state before chunk c
__global__ void k_scan2(int NC){
  int tid = blockIdx.x*blockDim.x + threadIdx.x;
  if(tid >= 512*16) return;
  int base = (tid >> 4)*NC*16 + (tid & 15);
  float h = 0.f;
  for(int c=0;c<NC;c++){
    int a = base + c*16;
    g_hI[a] = h;
    h = g_aP[a]*h + g_hE[a];
  }
}

// scan pass 3: rescan with init state, y[l] = sum_n h*C  (16-lane reduce)
__global__ void k_scan3(const float* __restrict__ alog, int L, int NC, int CH){
  int tid = blockIdx.x*blockDim.x + threadIdx.x;
  if(tid >= 512*NC*16) return;
  int n = tid & 15;
  int gid = tid >> 4;
  int c = gid % NC; int kd = gid / NC;
  int k = kd >> 7;
  float A = -__expf(alog[kd*16+n]);
  const float* dl = g_delta + kd*L;
  const float* us = g_xs + kd*L;
  const float* Bp = g_Bm + k*L*16 + n;
  const float* Cp = g_Cm + k*L*16 + n;
  float* ysp = g_ys + kd*L;
  int aidx = (kd*NC + c)*16 + n;
  float h = g_hI[aidx];
  int l0 = c*CH;
  for(int l=l0; l<l0+CH; l++){
    float dlt = dl[l];
    float dA = __expf(dlt*A);
    h = dA*h + dlt*Bp[l*16]*us[l];
    float pr = h*Cp[l*16];
    pr += __shfl_xor_sync(0xffffffffu, pr, 8);
    pr += __shfl_xor_sync(0xffffffffu, pr, 4);
    pr += __shfl_xor_sync(0xffffffffu, pr, 2);
    pr += __shfl_xor_sync(0xffffffffu, pr, 1);
    if(n == 0) ysp[l] = pr;
  }
}

// combine 4 directions (+ D*u per direction) back into spatial layout
__global__ void k_combine(const float* __restrict__ Dpw, int H, int W){
  int L = H*W;
  int idx = blockIdx.x*blockDim.x + threadIdx.x;
  if(idx >= 128*L) return;
  int p = idx % L; int d = idx / L;
  int hh = p / W, ww = p % W;
  int l1 = ww*H + hh;
  int lk0 = p, lk2 = L-1-p, lk3 = L-1-l1;
  float acc = 0.f;
  int o;
  o = (0*128+d)*L + lk0; acc += g_ys[o] + Dpw[0*128+d]*g_xs[o];
  o = (1*128+d)*L + l1;  acc += g_ys[o] + Dpw[1*128+d]*g_xs[o];
  o = (2*128+d)*L + lk2; acc += g_ys[o] + Dpw[2*128+d]*g_xs[o];
  o = (3*128+d)*L + lk3; acc += g_ys[o] + Dpw[3*128+d]*g_xs[o];
  g_yc[idx] = acc;
}

// out-norm (LN over 128 ch) * on_g + on_b, then * silu(z); in-place on g_yc
__global__ void k_outnorm(const float* __restrict__ og, const float* __restrict__ ob, int L){
  int p = blockIdx.x*blockDim.x + threadIdx.x;
  if(p >= L) return;
  float mu = 0.f;
  for(int d=0;d<128;d++) mu += g_yc[d*L+p];
  mu *= (1.0f/128.0f);
  float var = 0.f;
  for(int d=0;d<128;d++){ float df = g_yc[d*L+p]-mu; var += df*df; }
  var *= (1.0f/128.0f);
  float rs = rsqrtf(var + 1e-6f);
  for(int d=0;d<128;d++){
    float z = g_xz[(128+d)*L + p];
    g_yc[d*L+p] = ((g_yc[d*L+p]-mu)*rs*og[d] + ob[d]) * siluf(z);
  }
}

// out-proj 128->64 + residual (in-place on g_x)
__global__ void k_outproj(const float* __restrict__ opw, int L){
  int idx = blockIdx.x*blockDim.x + threadIdx.x;
  if(idx >= 64*L) return;
  int p = idx % L; int c = idx / L;
  float acc = g_x[idx];
  #pragma unroll 4
  for(int d=0;d<128;d++) acc += g_yc[d*L+p]*opw[d*64+c];
  g_x[idx] = acc;
}

// generic 64->64 3x3 conv, pad 1, stride s; optional silu; optional skip add
__global__ void k_conv3x3(int inid, const float* __restrict__ w, const float* __restrict__ b,
                          int skipid, int outid, float* extout,
                          int Hi, int Wi, int Ho, int Wo, int stride, int dosilu){
  int idx = blockIdx.x*blockDim.x + threadIdx.x;
  int LO = Ho*Wo;
  if(idx >= 64*LO) return;
  const float* in = bufptr(inid);
  float* out = (outid < 0) ? extout : bufptr(outid);
  int co = idx / LO; int pp = idx % LO;
  int oh = pp / Wo, ow = pp % Wo;
  float acc = b[co];
  const float* wc = w + co*64*9;
  int ihb = oh*stride - 1;
  int iwb = ow*stride - 1;
  for(int ci=0;ci<64;ci++){
    const float* ip = in + ci*Hi*Wi;
    const float* wp = wc + ci*9;
    #pragma unroll
    for(int i=0;i<3;i++){
      int ih = ihb + i;
      if(ih < 0 || ih >= Hi) continue;
      #pragma unroll
      for(int j=0;j<3;j++){
        int iw = iwb + j;
        if(iw < 0 || iw >= Wi) continue;
        acc += ip[ih*Wi+iw]*wp[i*3+j];
      }
    }
  }
  if(dosilu) acc = siluf(acc);
  if(skipid >= 0) acc += bufptr(skipid)[idx];
  out[idx] = acc;
}

// bilinear resize (half-pixel centers, clamped) on 64-channel maps
__global__ void k_resize(int inid, int outid, int Hi, int Wi, int Ho, int Wo){
  int idx = blockIdx.x*blockDim.x + threadIdx.x;
  int LO = Ho*Wo;
  if(idx >= 64*LO) return;
  const float* in = bufptr(inid);
  float* out = bufptr(outid);
  int c = idx / LO; int pp = idx % LO;
  int oh = pp / Wo, ow = pp % Wo;
  float fy = (oh + 0.5f)*((float)Hi/(float)Ho) - 0.5f;
  float fx = (ow + 0.5f)*((float)Wi/(float)Wo) - 0.5f;
  int y0 = (int)floorf(fy), x0 = (int)floorf(fx);
  float wy = fy - (float)y0, wx = fx - (float)x0;
  int y0c = max(y0, 0), y1c = min(y0+1, Hi-1);
  int x0c = max(x0, 0), x1c = min(x0+1, Wi-1);
  const float* ip = in + c*Hi*Wi;
  float v = (1.f-wy)*((1.f-wx)*ip[y0c*Wi+x0c] + wx*ip[y0c*Wi+x1c])
          +       wy*((1.f-wx)*ip[y1c*Wi+x0c] + wx*ip[y1c*Wi+x1c]);
  out[idx] = v;
}

__global__ void k_copy(int inid, int outid, int n){
  int i = blockIdx.x*blockDim.x + threadIdx.x;
  if(i < n) bufptr(outid)[i] = bufptr(inid)[i];
}

// ---------------- host orchestration ----------------
static inline int gs(int n, int bs){ return (n + bs - 1)/bs; }

extern "C" void kernel_launch(void* const* d_in, const int* in_sizes, int n_in,
                              void* d_out, int out_size){
  const float* E0     = (const float*)d_in[0];
  const float* pe_w   = (const float*)d_in[1];
  const float* pe_b   = (const float*)d_in[2];
  const float* pe_lg  = (const float*)d_in[3];
  const float* pe_lb  = (const float*)d_in[4];
  const float* ln_g   = (const float*)d_in[5];
  const float* ln_b   = (const float*)d_in[6];
  const float* in_w   = (const float*)d_in[7];
  const float* cv_w   = (const float*)d_in[8];
  const float* cv_b   = (const float*)d_in[9];
  const float* xp_w   = (const float*)d_in[10];
  const float* dt_w   = (const float*)d_in[11];
  const float* dt_b   = (const float*)d_in[12];
  const float* A_log  = (const float*)d_in[13];
  const float* Dp     = (const float*)d_in[14];
  const float* on_g   = (const float*)d_in[15];
  const float* on_b   = (const float*)d_in[16];
  const float* out_pw = (const float*)d_in[17];
  const float* dn_w   = (const float*)d_in[18];
  const float* dn_b   = (const float*)d_in[19];
  const float* dn_g   = (const float*)d_in[20];
  const float* dn_lb  = (const float*)d_in[21];
  const float* up_w   = (const float*)d_in[22];
  const float* up_b   = (const float*)d_in[23];
  const float* oc_w   = (const float*)d_in[24];
  const float* oc_b   = (const float*)d_in[25];

  const int BS = 256;

  // patch embed + LN
  k_patch_embed<<<gs(64*4096,BS),BS>>>(E0, pe_w, pe_b);
  k_ln2d<<<gs(4096,128),128>>>(0, 0, pe_lg, pe_lb, 64, 4096);

  auto vss = [&](int blk, int H){
    int W = H, L = H*W;
    k_ln2d      <<<gs(L,128),128>>>(0, 1, ln_g + blk*64, ln_b + blk*64, 64, L);
    k_inproj    <<<gs(256*L,BS),BS>>>(in_w + blk*64*256, L);
    k_dwconv_silu<<<gs(128*L,BS),BS>>>(cv_w + blk*128*9, cv_b + blk*128, H, W);
    k_build_xs  <<<gs(512*L,BS),BS>>>(H, W);
    k_xproj     <<<gs(4*36*L,BS),BS>>>(xp_w + blk*4*36*128, L);
    k_delta     <<<gs(512*L,BS),BS>>>(dt_w + blk*4*128*4, dt_b + blk*4*128, L);
    int NC = L/32; if(NC > 32) NC = 32; if(NC < 1) NC = 1;
    int CH = L/NC;
    k_scan1     <<<gs(512*NC*16,BS),BS>>>(A_log + blk*4*128*16, L, NC, CH);
    k_scan2     <<<gs(8192,BS),BS>>>(NC);
    k_scan3     <<<gs(512*NC*16,BS),BS>>>(A_log + blk*4*128*16, L, NC, CH);
    k_combine   <<<gs(128*L,BS),BS>>>(Dp + blk*4*128, H, W);
    k_outnorm   <<<gs(L,128),128>>>(on_g + blk*128, on_b + blk*128, L);
    k_outproj   <<<gs(64*L,BS),BS>>>(out_pw + blk*128*64, L);
  };

  const int skipid[3] = {4, 5, 6};
  int H = 64;
  for(int st=0; st<4; st++){
    vss(st*2,   H);
    vss(st*2+1, H);
    if(st < 3){
      k_copy<<<gs(64*H*H,BS),BS>>>(0, skipid[st], 64*H*H);
      int Ho = H/2;
      k_conv3x3<<<gs(64*Ho*Ho,BS),BS>>>(0, dn_w + st*64*64*9, dn_b + st*64,
                                        -1, 3, nullptr, H, H, Ho, Ho, 2, 0);
      k_ln2d<<<gs(Ho*Ho,128),128>>>(3, 0, dn_g + st*64, dn_lb + st*64, 64, Ho*Ho);
      H = Ho;
    }
  }

  // decoder: resize x2 -> conv+silu -> +skip
  for(int i=0;i<3;i++){
    int Ho = H*2;
    k_resize<<<gs(64*Ho*Ho,BS),BS>>>(0, 2, H, H, Ho, Ho);
    k_conv3x3<<<gs(64*Ho*Ho,BS),BS>>>(2, up_w + i*64*64*9, up_b + i*64,
                                      skipid[2-i], 0, nullptr, Ho, Ho, Ho, Ho, 1, 1);
    H = Ho;
  }

  // final: resize x4 (64 -> 256) -> conv + silu -> d_out
  k_resize<<<gs(64*256*256,BS),BS>>>(0, 2, 64, 64, 256, 256);
  k_conv3x3<<<gs(64*256*256,BS),BS>>>(2, oc_w, oc_b, -1, -1, (float*)d_out,
                                      256, 256, 256, 256, 1, 1);
}

// round 2
// speedup vs baseline: 1.1228x; 1.1228x over previous
#include <cuda_runtime.h>
#include <math.h>

// ---------------- static scratch (device globals; no allocation) ----------------
#define LMAX 4096
__device__ float g_x    [64*LMAX];
__device__ float g_h    [64*LMAX];
__device__ float g_t1   [64*256*256];
__device__ float g_t2   [64*128*128];
__device__ float g_s0   [64*4096];
__device__ float g_s1   [64*1024];
__device__ float g_s2   [64*256];
__device__ float g_xz   [256*LMAX];
__device__ float g_xconv[128*LMAX];
__device__ float g_xs   [4*128*LMAX];
__device__ float g_dts  [4*4*LMAX];
__device__ float g_Bm   [4*LMAX*16];
__device__ float g_Cm   [4*LMAX*16];
__device__ float g_delta[4*128*LMAX];
__device__ float g_aP   [4*128*32*16];
__device__ float g_hE   [4*128*32*16];
__device__ float g_hI   [4*128*32*16];
__device__ float g_ys   [4*128*LMAX];
__device__ float g_yc   [128*LMAX];

__device__ __forceinline__ float* bufptr(int id){
  switch(id){
    case 0: return g_x;
    case 1: return g_h;
    case 2: return g_t1;
    case 3: return g_t2;
    case 4: return g_s0;
    case 5: return g_s1;
    default: return g_s2;
  }
}

__device__ __forceinline__ float siluf(float x){ return x / (1.0f + __expf(-x)); }
__device__ __forceinline__ float softplusf(float x){ return (x > 20.0f) ? x : log1pf(__expf(x)); }

// ---------------- kernels ----------------

__global__ void k_patch_embed(const float* __restrict__ E0, const float* __restrict__ w,
                              const float* __restrict__ b){
  int idx = blockIdx.x*blockDim.x + threadIdx.x;
  if(idx >= 64*4096) return;
  int c = idx >> 12, p = idx & 4095;
  int oh = p >> 6, ow = p & 63;
  const float* wp = w + c*16;
  float acc = b[c];
  #pragma unroll
  for(int i=0;i<4;i++)
    #pragma unroll
    for(int j=0;j<4;j++)
      acc += E0[(oh*4+i)*256 + ow*4 + j] * wp[i*4+j];
  g_x[idx] = acc;
}

__global__ void k_ln2d(int inid, int outid, const float* __restrict__ g,
                       const float* __restrict__ b, int Cn, int L){
  int p = blockIdx.x*blockDim.x + threadIdx.x;
  if(p >= L) return;
  const float* in = bufptr(inid);
  float* out = bufptr(outid);
  float mu = 0.f;
  for(int c=0;c<Cn;c++) mu += in[c*L+p];
  mu /= (float)Cn;
  float var = 0.f;
  for(int c=0;c<Cn;c++){ float d = in[c*L+p]-mu; var += d*d; }
  var /= (float)Cn;
  float rs = rsqrtf(var + 1e-6f);
  for(int c=0;c<Cn;c++) out[c*L+p] = (in[c*L+p]-mu)*rs*g[c] + b[c];
}

// ---- naive projections (fallback for small L) ----
__global__ void k_inproj(const float* __restrict__ inw, int L){
  int idx = blockIdx.x*blockDim.x + threadIdx.x;
  if(idx >= 256*L) return;
  int e = idx / L, p = idx % L;
  float acc = 0.f;
  #pragma unroll 4
  for(int c=0;c<64;c++) acc += g_h[c*L+p]*inw[c*256+e];
  g_xz[idx] = acc;
}

__global__ void k_xproj(const float* __restrict__ xpw, int L){
  int idx = blockIdx.x*blockDim.x + threadIdx.x;
  if(idx >= 4*36*L) return;
  int l = idx % L; int kr = idx / L; int r = kr % 36; int k = kr / 36;
  const float* xs = g_xs + k*128*L + l;
  const float* w = xpw + (k*36+r)*128;
  float acc = 0.f;
  #pragma unroll 4
  for(int d=0;d<128;d++) acc += xs[d*L]*w[d];
  if(r < 4)       g_dts[(k*4+r)*L + l] = acc;
  else if(r < 20) g_Bm[(k*L+l)*16 + (r-4)] = acc;
  else            g_Cm[(k*L+l)*16 + (r-20)] = acc;
}

__global__ void k_outproj(const float* __restrict__ opw, int L){
  int idx = blockIdx.x*blockDim.x + threadIdx.x;
  if(idx >= 64*L) return;
  int p = idx % L; int c = idx / L;
  float acc = g_x[idx];
  #pragma unroll 4
  for(int d=0;d<128;d++) acc += g_yc[d*L+p]*opw[d*64+c];
  g_x[idx] = acc;
}

// ---- tiled projections (L multiple of 64, >=256) ----

// block 256 = 64 px * 4 e-groups of 16 e; grid (L/64, 4 e-chunks of 64)
__global__ void k_inproj_t(const float* __restrict__ inw, int L){
  __shared__ float sw_[64*64];
  int tid = threadIdx.x;
  int p0 = blockIdx.x*64;
  int e0 = blockIdx.y*64;
  for(int i=tid;i<64*64;i+=256){
    int c = i >> 6, e = i & 63;
    sw_[i] = inw[c*256 + e0 + e];
  }
  __syncthreads();
  int q  = tid & 63;
  int eg = tid >> 6;         // e = e0 + eg*16 + 0..15
  float acc[16];
  #pragma unroll
  for(int e=0;e<16;e++) acc[e]=0.f;
  int p = p0 + q;
  for(int c=0;c<64;c++){
    float h = g_h[c*L + p];
    const float* swc = sw_ + (c<<6) + eg*16;
    #pragma unroll
    for(int e=0;e<16;e++) acc[e] += h*swc[e];
  }
  #pragma unroll
  for(int e=0;e<16;e++)
    g_xz[(e0 + eg*16 + e)*L + p] = acc[e];
}

// block 256 = 64 l * 4 r-groups of 9; grid (L/64, 4 directions)
__global__ void k_xproj_t(const float* __restrict__ xpw, int L){
  __shared__ float sw_[36*128];
  int tid = threadIdx.x;
  int k = blockIdx.y;
  int p0 = blockIdx.x*64;
  for(int i=tid;i<36*128;i+=256)
    sw_[i] = xpw[k*36*128 + i];
  __syncthreads();
  int q  = tid & 63;
  int rg = tid >> 6;         // r = rg*9 .. rg*9+8
  int l = p0 + q;
  const float* xs = g_xs + k*128*L + l;
  float acc[9];
  #pragma unroll
  for(int r=0;r<9;r++) acc[r]=0.f;
  for(int d=0;d<128;d++){
    float xv = xs[d*L];
    const float* swd = sw_ + rg*9*128 + d;
    #pragma unroll
    for(int r=0;r<9;r++) acc[r] += xv*swd[r*128];
  }
  #pragma unroll
  for(int rr=0;rr<9;rr++){
    int r = rg*9+rr;
    float v = acc[rr];
    if(r < 4)       g_dts[(k*4+r)*L + l] = v;
    else if(r < 20) g_Bm[(k*L+l)*16 + (r-4)] = v;
    else            g_Cm[(k*L+l)*16 + (r-20)] = v;
  }
}

// block 256 = 64 px * 4 cg of 8 cout; grid (L/64, 2 chunks of 32 cout)
__global__ void k_outproj_t(const float* __restrict__ opw, int L){
  __shared__ float sw_[128*32];
  int tid = threadIdx.x;
  int p0 = blockIdx.x*64;
  int c0 = blockIdx.y*32;
  for(int i=tid;i<128*32;i+=256){
    int d = i >> 5, c = i & 31;
    sw_[i] = opw[d*64 + c0 + c];
  }
  __syncthreads();
  int q  = tid & 63;
  int cg = tid >> 6;     // cout = c0 + cg*8 + 0..7
  int p = p0 + q;
  float acc[8];
  #pragma unroll
  for(int c=0;c<8;c++) acc[c]=0.f;
  for(int d=0;d<128;d++){
    float y = g_yc[d*L + p];
    const float* swd = sw_ + (d<<5) + cg*8;
    #pragma unroll
    for(int c=0;c<8;c++) acc[c] += y*swd[c];
  }
  #pragma unroll
  for(int c=0;c<8;c++){
    int o = (c0 + cg*8 + c)*L + p;
    g_x[o] = g_x[o] + acc[c];
  }
}

__global__ void k_dwconv_silu(const float* __restrict__ w, const float* __restrict__ b,
                              int H, int W){
  int L = H*W;
  int idx = blockIdx.x*blockDim.x + threadIdx.x;
  if(idx >= 128*L) return;
  int d = idx / L, p = idx % L;
  int hh = p / W, ww = p % W;
  const float* in = g_xz + d*L;
  const float* wp = w + d*9;
  float acc = b[d];
  #pragma unroll
  for(int i=-1;i<=1;i++){
    int ih = hh+i; if(ih<0 || ih>=H) continue;
    #pragma unroll
    for(int j=-1;j<=1;j++){
      int iw = ww+j; if(iw<0 || iw>=W) continue;
      acc += in[ih*W+iw]*wp[(i+1)*3+(j+1)];
    }
  }
  g_xconv[idx] = siluf(acc);
}

__device__ __forceinline__ int permk(int k, int l, int H, int W, int L){
  if(k==0) return l;
  if(k==1) return (l%H)*W + l/H;
  if(k==2) return L-1-l;
  int l2 = L-1-l; return (l2%H)*W + l2/H;
}

__global__ void k_build_xs(int H, int W){
  int L = H*W;
  int idx = blockIdx.x*blockDim.x + threadIdx.x;
  if(idx >= 512*L) return;
  int l = idx % L; int kd = idx / L; int d = kd & 127; int k = kd >> 7;
  g_xs[idx] = g_xconv[d*L + permk(k,l,H,W,L)];
}

__global__ void k_delta(const float* __restrict__ dtw, const float* __restrict__ dtb, int L){
  int idx = blockIdx.x*blockDim.x + threadIdx.x;
  if(idx >= 512*L) return;
  int l = idx % L; int kd = idx / L; int k = kd >> 7;
  const float* w = dtw + kd*4;
  float acc = dtb[kd];
  #pragma unroll
  for(int r=0;r<4;r++) acc += g_dts[(k*4+r)*L + l]*w[r];
  g_delta[idx] = softplusf(acc);
}

__global__ void k_scan1(const float* __restrict__ alog, int L, int NC, int CH){
  int tid = blockIdx.x*blockDim.x + threadIdx.x;
  if(tid >= 512*NC*16) return;
  int n = tid & 15;
  int gid = tid >> 4;
  int c = gid % NC; int kd = gid / NC;
  int k = kd >> 7;
  float A = -__expf(alog[kd*16+n]);
  const float* dl = g_delta + kd*L;
  const float* us = g_xs + kd*L;
  const float* Bp = g_Bm + k*L*16 + n;
  float h = 0.f, sd = 0.f;
  int l0 = c*CH;
  for(int l=l0; l<l0+CH; l++){
    float dlt = dl[l];
    float dA = __expf(dlt*A);
    h = dA*h + dlt*Bp[l*16]*us[l];
    sd += dlt;
  }
  int aidx = (kd*NC + c)*16 + n;
  g_aP[aidx] = __expf(A*sd);
  g_hE[aidx] = h;
}

__global__ void k_scan2(int NC){
  int tid = blockIdx.x*blockDim.x + threadIdx.x;
  if(tid >= 512*16) return;
  int base = (tid >> 4)*NC*16 + (tid & 15);
  float h = 0.f;
  for(int c=0;c<NC;c++){
    int a = base + c*16;
    g_hI[a] = h;
    h = g_aP[a]*h + g_hE[a];
  }
}

__global__ void k_scan3(const float* __restrict__ alog, int L, int NC, int CH){
  int tid = blockIdx.x*blockDim.x + threadIdx.x;
  if(tid >= 512*NC*16) return;
  int n = tid & 15;
  int gid = tid >> 4;
  int c = gid % NC; int kd = gid / NC;
  int k = kd >> 7;
  float A = -__expf(alog[kd*16+n]);
  const float* dl = g_delta + kd*L;
  const float* us = g_xs + kd*L;
  const float* Bp = g_Bm + k*L*16 + n;
  const float* Cp = g_Cm + k*L*16 + n;
  float* ysp = g_ys + kd*L;
  int aidx = (kd*NC + c)*16 + n;
  float h = g_hI[aidx];
  int l0 = c*CH;
  for(int l=l0; l<l0+CH; l++){
    float dlt = dl[l];
    float dA = __expf(dlt*A);
    h = dA*h + dlt*Bp[l*16]*us[l];
    float pr = h*Cp[l*16];
    pr += __shfl_xor_sync(0xffffffffu, pr, 8);
    pr += __shfl_xor_sync(0xffffffffu, pr, 4);
    pr += __shfl_xor_sync(0xffffffffu, pr, 2);
    pr += __shfl_xor_sync(0xffffffffu, pr, 1);
    if(n == 0) ysp[l] = pr;
  }
}

__global__ void k_combine(const float* __restrict__ Dpw, int H, int W){
  int L = H*W;
  int idx = blockIdx.x*blockDim.x + threadIdx.x;
  if(idx >= 128*L) return;
  int p = idx % L; int d = idx / L;
  int hh = p / W, ww = p % W;
  int l1 = ww*H + hh;
  int lk0 = p, lk2 = L-1-p, lk3 = L-1-l1;
  float acc = 0.f;
  int o;
  o = (0*128+d)*L + lk0; acc += g_ys[o] + Dpw[0*128+d]*g_xs[o];
  o = (1*128+d)*L + l1;  acc += g_ys[o] + Dpw[1*128+d]*g_xs[o];
  o = (2*128+d)*L + lk2; acc += g_ys[o] + Dpw[2*128+d]*g_xs[o];
  o = (3*128+d)*L + lk3; acc += g_ys[o] + Dpw[3*128+d]*g_xs[o];
  g_yc[idx] = acc;
}

__global__ void k_outnorm(const float* __restrict__ og, const float* __restrict__ ob, int L){
  int p = blockIdx.x*blockDim.x + threadIdx.x;
  if(p >= L) return;
  float mu = 0.f;
  for(int d=0;d<128;d++) mu += g_yc[d*L+p];
  mu *= (1.0f/128.0f);
  float var = 0.f;
  for(int d=0;d<128;d++){ float df = g_yc[d*L+p]-mu; var += df*df; }
  var *= (1.0f/128.0f);
  float rs = rsqrtf(var + 1e-6f);
  for(int d=0;d<128;d++){
    float z = g_xz[(128+d)*L + p];
    g_yc[d*L+p] = ((g_yc[d*L+p]-mu)*rs*og[d] + ob[d]) * siluf(z);
  }
}

// ---- naive conv (stride 2 down convs only) ----
__global__ void k_conv3x3(int inid, const float* __restrict__ w, const float* __restrict__ b,
                          int skipid, int outid, float* extout,
                          int Hi, int Wi, int Ho, int Wo, int stride, int dosilu){
  int idx = blockIdx.x*blockDim.x + threadIdx.x;
  int LO = Ho*Wo;
  if(idx >= 64*LO) return;
  const float* in = bufptr(inid);
  float* out = (outid < 0) ? extout : bufptr(outid);
  int co = idx / LO; int pp = idx % LO;
  int oh = pp / Wo, ow = pp % Wo;
  float acc = b[co];
  const float* wc = w + co*64*9;
  int ihb = oh*stride - 1;
  int iwb = ow*stride - 1;
  for(int ci=0;ci<64;ci++){
    const float* ip = in + ci*Hi*Wi;
    const float* wp = wc + ci*9;
    #pragma unroll
    for(int i=0;i<3;i++){
      int ih = ihb + i;
      if(ih < 0 || ih >= Hi) continue;
      #pragma unroll
      for(int j=0;j<3;j++){
        int iw = iwb + j;
        if(iw < 0 || iw >= Wi) continue;
        acc += ip[ih*Wi+iw]*wp[i*3+j];
      }
    }
  }
  if(dosilu) acc = siluf(acc);
  if(skipid >= 0) acc += bufptr(skipid)[idx];
  out[idx] = acc;
}

// ---- tiled stride-1 conv: block 256, out tile 16co x 8h x 32w ----
// grid: (ceil(W/32), H/8, 4)
__global__ void k_conv3x3_t(int inid, const float* __restrict__ w, const float* __restrict__ b,
                            int skipid, int outid, float* __restrict__ extout,
                            int H, int W, int dosilu){
  __shared__ float sin_[10*35];
  __shared__ float sw_[16*9];
  const float* in = bufptr(inid);
  float* out = (outid < 0) ? extout : bufptr(outid);
  int tid = threadIdx.x;
  int qid = tid & 63;
  int cog = tid >> 6;         // 0..3, each handles 4 co
  int r   = qid >> 3;         // 0..7 output row within tile
  int q   = qid & 7;          // 0..7 quad of 4 cols
  int ox0 = blockIdx.x*32, oy0 = blockIdx.y*8;
  int cobase = blockIdx.z*16;
  float acc[4][4];
  #pragma unroll
  for(int i=0;i<4;i++)
    #pragma unroll
    for(int j=0;j<4;j++) acc[i][j]=0.f;

  for(int ci=0;ci<64;ci++){
    __syncthreads();
    const float* ip = in + ci*H*W;
    for(int i=tid;i<340;i+=256){
      int rr = i/34, cc = i%34;
      int gy = oy0-1+rr, gx = ox0-1+cc;
      float v = (gy>=0 && gy<H && gx>=0 && gx<W) ? ip[gy*W+gx] : 0.f;
      sin_[rr*35+cc] = v;
    }
    for(int i=tid;i<144;i+=256){
      int co = i/9, kk = i%9;
      sw_[i] = w[(cobase+co)*576 + ci*9 + kk];
    }
    __syncthreads();
    float inr[3][6];
    #pragma unroll
    for(int di=0;di<3;di++)
      #pragma unroll
      for(int dj=0;dj<6;dj++)
        inr[di][dj] = sin_[(r+di)*35 + 4*q + dj];
    #pragma unroll
    for(int co=0;co<4;co++){
      float wr[9];
      #pragma unroll
      for(int kk=0;kk<9;kk++) wr[kk] = sw_[(cog*4+co)*9 + kk];
      #pragma unroll
      for(int px=0;px<4;px++){
        float s = acc[co][px];
        #pragma unroll
        for(int di=0;di<3;di++)
          #pragma unroll
          for(int dj=0;dj<3;dj++)
            s += wr[di*3+dj]*inr[di][dj+px];
        acc[co][px] = s;
      }
    }
  }

  int gy = oy0 + r;
  #pragma unroll
  for(int co=0;co<4;co++){
    int c = cobase + cog*4 + co;
    float bb = b[c];
    #pragma unroll
    for(int px=0;px<4;px++){
      int gx = ox0 + 4*q + px;
      if(gy < H && gx < W){
        float v = acc[co][px] + bb;
        if(dosilu) v = siluf(v);
        int o = c*H*W + gy*W + gx;
        if(skipid >= 0) v += bufptr(skipid)[o];
        out[o] = v;
      }
    }
  }
}

__global__ void k_resize(int inid, int outid, int Hi, int Wi, int Ho, int Wo){
  int idx = blockIdx.x*blockDim.x + threadIdx.x;
  int LO = Ho*Wo;
  if(idx >= 64*LO) return;
  const float* in = bufptr(inid);
  float* out = bufptr(outid);
  int c = idx / LO; int pp = idx % LO;
  int oh = pp / Wo, ow = pp % Wo;
  float fy = (oh + 0.5f)*((float)Hi/(float)Ho) - 0.5f;
  float fx = (ow + 0.5f)*((float)Wi/(float)Wo) - 0.5f;
  int y0 = (int)floorf(fy), x0 = (int)floorf(fx);
  float wy = fy - (float)y0, wx = fx - (float)x0;
  int y0c = max(y0, 0), y1c = min(y0+1, Hi-1);
  int x0c = max(x0, 0), x1c = min(x0+1, Wi-1);
  const float* ip = in + c*Hi*Wi;
  float v = (1.f-wy)*((1.f-wx)*ip[y0c*Wi+x0c] + wx*ip[y0c*Wi+x1c])
          +       wy*((1.f-wx)*ip[y1c*Wi+x0c] + wx*ip[y1c*Wi+x1c]);
  out[idx] = v;
}

__global__ void k_copy(int inid, int outid, int n){
  int i = blockIdx.x*blockDim.x + threadIdx.x;
  if(i < n) bufptr(outid)[i] = bufptr(inid)[i];
}

// ---------------- host orchestration ----------------
static inline int gs(int n, int bs){ return (n + bs - 1)/bs; }

extern "C" void kernel_launch(void* const* d_in, const int* in_sizes, int n_in,
                              void* d_out, int out_size){
  const float* E0     = (const float*)d_in[0];
  const float* pe_w   = (const float*)d_in[1];
  const float* pe_b   = (const float*)d_in[2];
  const float* pe_lg  = (const float*)d_in[3];
  const float* pe_lb  = (const float*)d_in[4];
  const float* ln_g   = (const float*)d_in[5];
  const float* ln_b   = (const float*)d_in[6];
  const float* in_w   = (const float*)d_in[7];
  const float* cv_w   = (const float*)d_in[8];
  const float* cv_b   = (const float*)d_in[9];
  const float* xp_w   = (const float*)d_in[10];
  const float* dt_w   = (const float*)d_in[11];
  const float* dt_b   = (const float*)d_in[12];
  const float* A_log  = (const float*)d_in[13];
  const float* Dp     = (const float*)d_in[14];
  const float* on_g   = (const float*)d_in[15];
  const float* on_b   = (const float*)d_in[16];
  const float* out_pw = (const float*)d_in[17];
  const float* dn_w   = (const float*)d_in[18];
  const float* dn_b   = (const float*)d_in[19];
  const float* dn_g   = (const float*)d_in[20];
  const float* dn_lb  = (const float*)d_in[21];
  const float* up_w   = (const float*)d_in[22];
  const float* up_b   = (const float*)d_in[23];
  const float* oc_w   = (const float*)d_in[24];
  const float* oc_b   = (const float*)d_in[25];

  const int BS = 256;

  k_patch_embed<<<gs(64*4096,BS),BS>>>(E0, pe_w, pe_b);
  k_ln2d<<<gs(4096,128),128>>>(0, 0, pe_lg, pe_lb, 64, 4096);

  auto vss = [&](int blk, int H){
    int W = H, L = H*W;
    k_ln2d      <<<gs(L,128),128>>>(0, 1, ln_g + blk*64, ln_b + blk*64, 64, L);
    if(L >= 256){
      k_inproj_t<<<dim3(L/64, 4), 256>>>(in_w + blk*64*256, L);
    } else {
      k_inproj  <<<gs(256*L,BS),BS>>>(in_w + blk*64*256, L);
    }
    k_dwconv_silu<<<gs(128*L,BS),BS>>>(cv_w + blk*128*9, cv_b + blk*128, H, W);
    k_build_xs  <<<gs(512*L,BS),BS>>>(H, W);
    if(L >= 256){
      k_xproj_t <<<dim3(L/64, 4), 256>>>(xp_w + blk*4*36*128, L);
    } else {
      k_xproj   <<<gs(4*36*L,BS),BS>>>(xp_w + blk*4*36*128, L);
    }
    k_delta     <<<gs(512*L,BS),BS>>>(dt_w + blk*4*128*4, dt_b + blk*4*128, L);
    int NC = L/32; if(NC > 32) NC = 32; if(NC < 1) NC = 1;
    int CH = L/NC;
    k_scan1     <<<gs(512*NC*16,BS),BS>>>(A_log + blk*4*128*16, L, NC, CH);
    k_scan2     <<<gs(8192,BS),BS>>>(NC);
    k_scan3     <<<gs(512*NC*16,BS),BS>>>(A_log + blk*4*128*16, L, NC, CH);
    k_combine   <<<gs(128*L,BS),BS>>>(Dp + blk*4*128, H, W);
    k_outnorm   <<<gs(L,128),128>>>(on_g + blk*128, on_b + blk*128, L);
    if(L >= 256){
      k_outproj_t<<<dim3(L/64, 2), 256>>>(out_pw + blk*128*64, L);
    } else {
      k_outproj <<<gs(64*L,BS),BS>>>(out_pw + blk*128*64, L);
    }
  };

  const int skipid[3] = {4, 5, 6};
  int H = 64;
  for(int st=0; st<4; st++){
    vss(st*2,   H);
    vss(st*2+1, H);
    if(st < 3){
      k_copy<<<gs(64*H*H,BS),BS>>>(0, skipid[st], 64*H*H);
      int Ho = H/2;
      k_conv3x3<<<gs(64*Ho*Ho,BS),BS>>>(0, dn_w + st*64*64*9, dn_b + st*64,
                                        -1, 3, nullptr, H, H, Ho, Ho, 2, 0);
      k_ln2d<<<gs(Ho*Ho,128),128>>>(3, 0, dn_g + st*64, dn_lb + st*64, 64, Ho*Ho);
      H = Ho;
    }
  }

  for(int i=0;i<3;i++){
    int Ho = H*2;
    k_resize<<<gs(64*Ho*Ho,BS),BS>>>(0, 2, H, H, Ho, Ho);
    dim3 gconv((Ho+31)/32, Ho/8, 4);
    k_conv3x3_t<<<gconv,256>>>(2, up_w + i*64*64*9, up_b + i*64,
                               skipid[2-i], 0, nullptr, Ho, Ho, 1);
    H = Ho;
  }

  k_resize<<<gs(64*256*256,BS),BS>>>(0, 2, 64, 64, 256, 256);
  dim3 gfin(8, 32, 4);
  k_conv3x3_t<<<gfin,256>>>(2, oc_w, oc_b, -1, -1, (float*)d_out, 256, 256, 1);
}

// round 3
// speedup vs baseline: 1.3169x; 1.1729x over previous
#include <cuda_runtime.h>
#include <math.h>

#define LMAX 4096
__device__ float g_x    [64*LMAX];        // current feature map
__device__ float g_t1   [64*256*256];     // decoder ping-pong
__device__ float g_t2   [64*128*128];     // down-conv temp
__device__ float g_s0   [64*4096];
__device__ float g_s1   [64*1024];
__device__ float g_s2   [64*256];
__device__ float g_xz   [256*LMAX];       // xc rows 0..127, z rows 128..255
__device__ float g_x1   [128*LMAX];       // dwconv+silu output (row-major)
__device__ float g_x2   [128*LMAX];       // transposed copy
__device__ float g_Bm   [4*LMAX*16];
__device__ float g_Cm   [4*LMAX*16];
__device__ float g_delta[4*128*LMAX];
__device__ float g_aP   [4*128*64*16];
__device__ float g_hE   [4*128*64*16];
__device__ float g_hI   [4*128*64*16];
__device__ float g_ys   [4*128*LMAX];
__device__ float g_yc   [128*LMAX];

__device__ __forceinline__ float* bufptr(int id){
  switch(id){
    case 0: return g_x;
    case 2: return g_t1;
    case 3: return g_t2;
    case 4: return g_s0;
    case 5: return g_s1;
    default: return g_s2;
  }
}

__device__ __forceinline__ float siluf(float x){ return x / (1.0f + __expf(-x)); }
__device__ __forceinline__ float softplusf(float x){ return (x > 20.0f) ? x : log1pf(__expf(x)); }

// ---------------- kernels ----------------

__global__ void k_patch_embed(const float* __restrict__ E0, const float* __restrict__ w,
                              const float* __restrict__ b){
  int idx = blockIdx.x*blockDim.x + threadIdx.x;
  if(idx >= 64*4096) return;
  int c = idx >> 12, p = idx & 4095;
  int oh = p >> 6, ow = p & 63;
  const float* wp = w + c*16;
  float acc = b[c];
  #pragma unroll
  for(int i=0;i<4;i++)
    #pragma unroll
    for(int j=0;j<4;j++)
      acc += E0[(oh*4+i)*256 + ow*4 + j] * wp[i*4+j];
  g_x[idx] = acc;
}

__global__ void k_ln2d(int inid, int outid, const float* __restrict__ g,
                       const float* __restrict__ b, int Cn, int L){
  int p = blockIdx.x*blockDim.x + threadIdx.x;
  if(p >= L) return;
  const float* in = bufptr(inid);
  float* out = bufptr(outid);
  float mu = 0.f;
  #pragma unroll 4
  for(int c=0;c<Cn;c++) mu += in[c*L+p];
  mu /= (float)Cn;
  float var = 0.f;
  #pragma unroll 4
  for(int c=0;c<Cn;c++){ float d = in[c*L+p]-mu; var += d*d; }
  var /= (float)Cn;
  float rs = rsqrtf(var + 1e-6f);
  for(int c=0;c<Cn;c++) out[c*L+p] = (in[c*L+p]-mu)*rs*g[c] + b[c];
}

// fused LN (over 64 ch) + in-proj (64 -> 64 e-chunk). grid(L/64, 4), block 256
__global__ void k_ln_inproj(const float* __restrict__ inw, const float* __restrict__ lng,
                            const float* __restrict__ lnb, int L){
  __shared__ float sh[64*65];
  __shared__ float sw[64*64];
  __shared__ float sg[64], sb[64];
  __shared__ float red[4*64];
  __shared__ float smu[64], srs[64];
  int tid = threadIdx.x;
  int p0 = blockIdx.x*64;
  int e0 = blockIdx.y*64;
  for(int i=tid;i<4096;i+=256){ int c=i>>6, p=i&63; sh[c*65+p] = g_x[c*L + p0 + p]; }
  for(int i=tid;i<4096;i+=256){ int c=i>>6, e=i&63; sw[i] = inw[c*256 + e0 + e]; }
  if(tid < 64){ sg[tid]=lng[tid]; sb[tid]=lnb[tid]; }
  __syncthreads();
  int t4 = tid>>6, px = tid&63;
  // pass 1: mean
  float s = 0.f;
  #pragma unroll
  for(int cc=0;cc<16;cc++) s += sh[(t4*16+cc)*65+px];
  red[t4*64+px] = s;
  __syncthreads();
  if(t4==0){
    float a = red[px]+red[64+px]+red[128+px]+red[192+px];
    smu[px] = a*(1.0f/64.0f);
  }
  __syncthreads();
  // pass 2: variance (two-pass for precision)
  float mu = smu[px];
  float ss = 0.f;
  #pragma unroll
  for(int cc=0;cc<16;cc++){ float d = sh[(t4*16+cc)*65+px]-mu; ss += d*d; }
  red[t4*64+px] = ss;
  __syncthreads();
  if(t4==0){
    float a = red[px]+red[64+px]+red[128+px]+red[192+px];
    srs[px] = rsqrtf(a*(1.0f/64.0f) + 1e-6f);
  }
  __syncthreads();
  for(int i=tid;i<4096;i+=256){ int c=i>>6, p=i&63;
    sh[c*65+p] = (sh[c*65+p]-smu[p])*srs[p]*sg[c] + sb[c]; }
  __syncthreads();
  int q = tid&63, eg = tid>>6;
  float acc[16];
  #pragma unroll
  for(int e=0;e<16;e++) acc[e]=0.f;
  #pragma unroll 4
  for(int c=0;c<64;c++){
    float h = sh[c*65+q];
    const float* wp = sw + c*64 + eg*16;
    #pragma unroll
    for(int e=0;e<16;e++) acc[e] += h*wp[e];
  }
  #pragma unroll
  for(int e=0;e<16;e++)
    g_xz[(e0 + eg*16 + e)*L + p0 + q] = acc[e];
}

// depthwise 3x3 + silu; writes row-major (x1) AND transposed (x2)
__global__ void k_dwconv_tr(const float* __restrict__ w, const float* __restrict__ b,
                            int H, int W){
  int L = H*W;
  int idx = blockIdx.x*blockDim.x + threadIdx.x;
  if(idx >= 128*L) return;
  int d = idx / L, p = idx % L;
  int hh = p / W, ww = p % W;
  const float* in = g_xz + d*L;
  const float* wp = w + d*9;
  float acc = b[d];
  #pragma unroll
  for(int i=-1;i<=1;i++){
    int ih = hh+i; if(ih<0 || ih>=H) continue;
    #pragma unroll
    for(int j=-1;j<=1;j++){
      int iw = ww+j; if(iw<0 || iw>=W) continue;
      acc += in[ih*W+iw]*wp[(i+1)*3+(j+1)];
    }
  }
  float v = siluf(acc);
  g_x1[idx] = v;
  g_x2[d*L + ww*H + hh] = v;
}

// fused x-proj (128->36) + delta. grid(L/64, 4 dirs), block 256
__global__ void k_xprojdelta(const float* __restrict__ xpw, const float* __restrict__ dtw,
                             const float* __restrict__ dtb, int L){
  __shared__ float xt[64*64];        // half of d (64 rows x 64 px)
  __shared__ float sw[36*128];       // [r*128 + d]
  __shared__ float sdts[4*64];
  __shared__ float sdtw[128*4];
  __shared__ float sdtb[128];
  int tid = threadIdx.x;
  int k = blockIdx.y;
  int p0 = blockIdx.x*64;
  bool rev = (k >= 2);
  const float* base = (k & 1) ? g_x2 : g_x1;
  for(int i=tid;i<4608;i+=256) sw[i] = xpw[k*4608 + i];
  for(int i=tid;i<512;i+=256) sdtw[i] = dtw[k*512 + i];
  if(tid < 128) sdtb[tid] = dtb[k*128 + tid];

  int q = tid&63, rg = tid>>6;
  float acc[9];
  #pragma unroll
  for(int j=0;j<9;j++) acc[j]=0.f;

  for(int half=0; half<2; half++){
    __syncthreads();
    for(int i=tid;i<4096;i+=256){
      int d = i>>6, qq = i&63;
      int l = p0 + qq;
      int gl = rev ? (L-1-l) : l;
      xt[i] = base[(half*64+d)*L + gl];
    }
    __syncthreads();
    #pragma unroll 2
    for(int d=0;d<64;d++){
      float xv = xt[d*64+q];
      const float* wp = sw + half*64 + d + rg*9*128;
      #pragma unroll
      for(int j=0;j<9;j++) acc[j] += xv*wp[j*128];
    }
  }
  int l = p0 + q;
  #pragma unroll
  for(int j=0;j<9;j++){
    int r = rg*9 + j;
    if(r < 4)       sdts[r*64+q] = acc[j];
    else if(r < 20) g_Bm[(k*L+l)*16 + (r-4)]  = acc[j];
    else            g_Cm[(k*L+l)*16 + (r-20)] = acc[j];
  }
  __syncthreads();
  int dg = tid>>6, q2 = tid&63;
  #pragma unroll 4
  for(int dd=0; dd<32; dd++){
    int d = dg*32 + dd;
    float a = sdtb[d];
    #pragma unroll
    for(int r=0;r<4;r++) a += sdts[r*64+q2]*sdtw[d*4+r];
    g_delta[(k*128+d)*L + p0 + q2] = softplusf(a);
  }
}

// scan pass 1
__global__ void k_scan1(const float* __restrict__ alog, int L, int NC, int CH){
  int tid = blockIdx.x*blockDim.x + threadIdx.x;
  if(tid >= 512*NC*16) return;
  int n = tid & 15;
  int gid = tid >> 4;
  int c = gid % NC; int kd = gid / NC;
  int k = kd >> 7, d = kd & 127;
  float A = -__expf(alog[kd*16+n]);
  const float* dl = g_delta + kd*L;
  const float* up = ((k & 1) ? g_x2 : g_x1) + d*L;
  bool rev = (k >= 2);
  const float* Bp = g_Bm + k*L*16 + n;
  float h = 0.f, sd = 0.f;
  int l0 = c*CH;
  #pragma unroll 4
  for(int l=l0; l<l0+CH; l++){
    float dlt = dl[l];
    float uv = up[rev ? (L-1-l) : l];
    float dA = __expf(dlt*A);
    h = dA*h + dlt*Bp[l*16]*uv;
    sd += dlt;
  }
  int aidx = (kd*NC + c)*16 + n;
  g_aP[aidx] = __expf(A*sd);
  g_hE[aidx] = h;
}

__global__ void k_scan2(int NC){
  int tid = blockIdx.x*blockDim.x + threadIdx.x;
  if(tid >= 512*16) return;
  int base = (tid >> 4)*NC*16 + (tid & 15);
  float h = 0.f;
  for(int c=0;c<NC;c++){
    int a = base + c*16;
    g_hI[a] = h;
    h = g_aP[a]*h + g_hE[a];
  }
}

__global__ void k_scan3(const float* __restrict__ alog, int L, int NC, int CH){
  int tid = blockIdx.x*blockDim.x + threadIdx.x;
  if(tid >= 512*NC*16) return;
  int n = tid & 15;
  int gid = tid >> 4;
  int c = gid % NC; int kd = gid / NC;
  int k = kd >> 7, d = kd & 127;
  float A = -__expf(alog[kd*16+n]);
  const float* dl = g_delta + kd*L;
  const float* up = ((k & 1) ? g_x2 : g_x1) + d*L;
  bool rev = (k >= 2);
  const float* Bp = g_Bm + k*L*16 + n;
  const float* Cp = g_Cm + k*L*16 + n;
  float* ysp = g_ys + kd*L;
  int aidx = (kd*NC + c)*16 + n;
  float h = g_hI[aidx];
  int l0 = c*CH;
  #pragma unroll 2
  for(int l=l0; l<l0+CH; l++){
    float dlt = dl[l];
    float uv = up[rev ? (L-1-l) : l];
    float dA = __expf(dlt*A);
    h = dA*h + dlt*Bp[l*16]*uv;
    float pr = h*Cp[l*16];
    pr += __shfl_xor_sync(0xffffffffu, pr, 8);
    pr += __shfl_xor_sync(0xffffffffu, pr, 4);
    pr += __shfl_xor_sync(0xffffffffu, pr, 2);
    pr += __shfl_xor_sync(0xffffffffu, pr, 1);
    if(n == 0) ysp[l] = pr;
  }
}

// fused combine(4 dirs) + out-LN(128) + *silu(z). grid(L/32), block 256
__global__ void k_post(const float* __restrict__ Dpw, const float* __restrict__ og,
                       const float* __restrict__ ob, int L, int H, int W){
  __shared__ float sds[128], sog[128], sob[128];
  __shared__ float red[8*32];
  __shared__ float smu[32], srs[32];
  int tid = threadIdx.x;
  if(tid < 128){
    sds[tid] = Dpw[tid] + Dpw[128+tid] + Dpw[256+tid] + Dpw[384+tid];
    sog[tid] = og[tid]; sob[tid] = ob[tid];
  }
  __syncthreads();
  int p = tid & 31, dg = tid >> 5;
  int pp = blockIdx.x*32 + p;
  int hh = pp / W, ww = pp % W;
  int l1 = ww*H + hh, l2 = L-1-pp, l3 = L-1-l1;
  float v[16];
  float s = 0.f;
  #pragma unroll
  for(int dd=0;dd<16;dd++){
    int d = dg*16 + dd;
    float a = g_ys[d*L + pp] + g_ys[(128+d)*L + l1]
            + g_ys[(256+d)*L + l2] + g_ys[(384+d)*L + l3]
            + sds[d]*g_x1[d*L + pp];
    v[dd] = a; s += a;
  }
  red[dg*32+p] = s;
  __syncthreads();
  if(dg == 0){
    float a = 0.f;
    #pragma unroll
    for(int j=0;j<8;j++) a += red[j*32+p];
    smu[p] = a*(1.0f/128.0f);
  }
  __syncthreads();
  float mu = smu[p];
  float ss = 0.f;
  #pragma unroll
  for(int dd=0;dd<16;dd++){ float df = v[dd]-mu; ss += df*df; }
  red[dg*32+p] = ss;
  __syncthreads();
  if(dg == 0){
    float a = 0.f;
    #pragma unroll
    for(int j=0;j<8;j++) a += red[j*32+p];
    srs[p] = rsqrtf(a*(1.0f/128.0f) + 1e-6f);
  }
  __syncthreads();
  float rs = srs[p];
  #pragma unroll
  for(int dd=0;dd<16;dd++){
    int d = dg*16 + dd;
    float z = g_xz[(128+d)*L + pp];
    g_yc[d*L + pp] = ((v[dd]-mu)*rs*sog[d] + sob[d]) * siluf(z);
  }
}

// out-proj 128->64 + residual; optional skip store. grid(L/64, 2), block 256
__global__ void k_outproj_t(const float* __restrict__ opw, int L, int skipid){
  __shared__ float sw[128*32];
  int tid = threadIdx.x;
  int p0 = blockIdx.x*64;
  int c0 = blockIdx.y*32;
  for(int i=tid;i<4096;i+=256){
    int d = i >> 5, c = i & 31;
    sw[i] = opw[d*64 + c0 + c];
  }
  __syncthreads();
  int q = tid & 63;
  int cg = tid >> 6;
  int p = p0 + q;
  float acc[8];
  #pragma unroll
  for(int c=0;c<8;c++) acc[c]=0.f;
  #pragma unroll 4
  for(int d=0;d<128;d++){
    float y = g_yc[d*L + p];
    const float* wp = sw + (d<<5) + cg*8;
    #pragma unroll
    for(int c=0;c<8;c++) acc[c] += y*wp[c];
  }
  float* skp = (skipid >= 0) ? bufptr(skipid) : nullptr;
  #pragma unroll
  for(int c=0;c<8;c++){
    int o = (c0 + cg*8 + c)*L + p;
    float r = g_x[o] + acc[c];
    g_x[o] = r;
    if(skp) skp[o] = r;
  }
}

// naive conv (stride-2 downs only)
__global__ void k_conv3x3(int inid, const float* __restrict__ w, const float* __restrict__ b,
                          int outid, int Hi, int Wi, int Ho, int Wo, int stride){
  int idx = blockIdx.x*blockDim.x + threadIdx.x;
  int LO = Ho*Wo;
  if(idx >= 64*LO) return;
  const float* in = bufptr(inid);
  float* out = bufptr(outid);
  int co = idx / LO; int pp = idx % LO;
  int oh = pp / Wo, ow = pp % Wo;
  float acc = b[co];
  const float* wc = w + co*64*9;
  int ihb = oh*stride - 1;
  int iwb = ow*stride - 1;
  for(int ci=0;ci<64;ci++){
    const float* ip = in + ci*Hi*Wi;
    const float* wp = wc + ci*9;
    #pragma unroll
    for(int i=0;i<3;i++){
      int ih = ihb + i;
      if(ih < 0 || ih >= Hi) continue;
      #pragma unroll
      for(int j=0;j<3;j++){
        int iw = iwb + j;
        if(iw < 0 || iw >= Wi) continue;
        acc += ip[ih*Wi+iw]*wp[i*3+j];
      }
    }
  }
  out[idx] = acc;
}

// tiled conv with fused bilinear-resized input. out tile 16co x 8h x 32w
// grid: (ceil(W/32), H/8, 4)
__global__ void k_conv3x3_rt(int inid, const float* __restrict__ w, const float* __restrict__ b,
                             int skipid, int outid, float* __restrict__ extout,
                             int Hi, int Wi, int H, int W, int dosilu){
  __shared__ float sin_[10*35];
  __shared__ float sw_[16*9];
  const float* in = bufptr(inid);
  float* out = (outid < 0) ? extout : bufptr(outid);
  int tid = threadIdx.x;
  int qid = tid & 63;
  int cog = tid >> 6;
  int r   = qid >> 3;
  int q   = qid & 7;
  int ox0 = blockIdx.x*32, oy0 = blockIdx.y*8;
  int cobase = blockIdx.z*16;
  float sy = (float)Hi/(float)H, sx = (float)Wi/(float)W;
  float acc[4][4];
  #pragma unroll
  for(int i=0;i<4;i++)
    #pragma unroll
    for(int j=0;j<4;j++) acc[i][j]=0.f;

  for(int ci=0;ci<64;ci++){
    __syncthreads();
    const float* ip = in + ci*Hi*Wi;
    for(int i=tid;i<340;i+=256){
      int rr = i/34, cc = i%34;
      int oy = oy0-1+rr, ox = ox0-1+cc;
      float v = 0.f;
      if(oy>=0 && oy<H && ox>=0 && ox<W){
        float fy = (oy + 0.5f)*sy - 0.5f;
        float fx = (ox + 0.5f)*sx - 0.5f;
        int y0 = (int)floorf(fy), x0 = (int)floorf(fx);
        float wy = fy - (float)y0, wx = fx - (float)x0;
        int y0c = max(y0,0), y1c = min(y0+1, Hi-1);
        int x0c = max(x0,0), x1c = min(x0+1, Wi-1);
        v = (1.f-wy)*((1.f-wx)*ip[y0c*Wi+x0c] + wx*ip[y0c*Wi+x1c])
          +       wy*((1.f-wx)*ip[y1c*Wi+x0c] + wx*ip[y1c*Wi+x1c]);
      }
      sin_[rr*35+cc] = v;
    }
    for(int i=tid;i<144;i+=256){
      int co = i/9, kk = i%9;
      sw_[i] = w[(cobase+co)*576 + ci*9 + kk];
    }
    __syncthreads();
    float inr[3][6];
    #pragma unroll
    for(int di=0;di<3;di++)
      #pragma unroll
      for(int dj=0;dj<6;dj++)
        inr[di][dj] = sin_[(r+di)*35 + 4*q + dj];
    #pragma unroll
    for(int co=0;co<4;co++){
      float wr[9];
      #pragma unroll
      for(int kk=0;kk<9;kk++) wr[kk] = sw_[(cog*4+co)*9 + kk];
      #pragma unroll
      for(int px=0;px<4;px++){
        float sacc = acc[co][px];
        #pragma unroll
        for(int di=0;di<3;di++)
          #pragma unroll
          for(int dj=0;dj<3;dj++)
            sacc += wr[di*3+dj]*inr[di][dj+px];
        acc[co][px] = sacc;
      }
    }
  }

  int gy = oy0 + r;
  #pragma unroll
  for(int co=0;co<4;co++){
    int c = cobase + cog*4 + co;
    float bb = b[c];
    #pragma unroll
    for(int px=0;px<4;px++){
      int gx = ox0 + 4*q + px;
      if(gy < H && gx < W){
        float v = acc[co][px] + bb;
        if(dosilu) v = siluf(v);
        int o = c*H*W + gy*W + gx;
        if(skipid >= 0) v += bufptr(skipid)[o];
        out[o] = v;
      }
    }
  }
}

// ---------------- host orchestration ----------------
static inline int gs(int n, int bs){ return (n + bs - 1)/bs; }

extern "C" void kernel_launch(void* const* d_in, const int* in_sizes, int n_in,
                              void* d_out, int out_size){
  const float* E0     = (const float*)d_in[0];
  const float* pe_w   = (const float*)d_in[1];
  const float* pe_b   = (const float*)d_in[2];
  const float* pe_lg  = (const float*)d_in[3];
  const float* pe_lb  = (const float*)d_in[4];
  const float* ln_g   = (const float*)d_in[5];
  const float* ln_b   = (const float*)d_in[6];
  const float* in_w   = (const float*)d_in[7];
  const float* cv_w   = (const float*)d_in[8];
  const float* cv_b   = (const float*)d_in[9];
  const float* xp_w   = (const float*)d_in[10];
  const float* dt_w   = (const float*)d_in[11];
  const float* dt_b   = (const float*)d_in[12];
  const float* A_log  = (const float*)d_in[13];
  const float* Dp     = (const float*)d_in[14];
  const float* on_g   = (const float*)d_in[15];
  const float* on_b   = (const float*)d_in[16];
  const float* out_pw = (const float*)d_in[17];
  const float* dn_w   = (const float*)d_in[18];
  const float* dn_b   = (const float*)d_in[19];
  const float* dn_g   = (const float*)d_in[20];
  const float* dn_lb  = (const float*)d_in[21];
  const float* up_w   = (const float*)d_in[22];
  const float* up_b   = (const float*)d_in[23];
  const float* oc_w   = (const float*)d_in[24];
  const float* oc_b   = (const float*)d_in[25];

  const int BS = 256;

  k_patch_embed<<<gs(64*4096,BS),BS>>>(E0, pe_w, pe_b);
  k_ln2d<<<gs(4096,128),128>>>(0, 0, pe_lg, pe_lb, 64, 4096);

  auto vss = [&](int blk, int H, int skipid){
    int W = H, L = H*W;
    k_ln_inproj <<<dim3(L/64,4),256>>>(in_w + blk*64*256, ln_g + blk*64, ln_b + blk*64, L);
    k_dwconv_tr <<<gs(128*L,BS),BS>>>(cv_w + blk*128*9, cv_b + blk*128, H, W);
    k_xprojdelta<<<dim3(L/64,4),256>>>(xp_w + blk*4*36*128, dt_w + blk*4*128*4,
                                       dt_b + blk*4*128, L);
    int NC = L/64; if(NC < 1) NC = 1;
    int CH = L/NC;
    k_scan1<<<gs(512*NC*16,BS),BS>>>(A_log + blk*4*128*16, L, NC, CH);
    k_scan2<<<gs(8192,BS),BS>>>(NC);
    k_scan3<<<gs(512*NC*16,BS),BS>>>(A_log + blk*4*128*16, L, NC, CH);
    k_post <<<L/32,256>>>(Dp + blk*4*128, on_g + blk*128, on_b + blk*128, L, H, W);
    k_outproj_t<<<dim3(L/64,2),256>>>(out_pw + blk*128*64, L, skipid);
  };

  const int skipid[3] = {4, 5, 6};
  int H = 64;
  for(int st=0; st<4; st++){
    vss(st*2,   H, -1);
    vss(st*2+1, H, (st < 3) ? skipid[st] : -1);
    if(st < 3){
      int Ho = H/2;
      k_conv3x3<<<gs(64*Ho*Ho,BS),BS>>>(0, dn_w + st*64*64*9, dn_b + st*64,
                                        3, H, H, Ho, Ho, 2);
      k_ln2d<<<gs(Ho*Ho,128),128>>>(3, 0, dn_g + st*64, dn_lb + st*64, 64, Ho*Ho);
      H = Ho;
    }
  }

  // decoder: fused (bilinear x2 resize + conv + silu + skip), ping-pong 0 <-> 2
  int cur = 0;
  for(int i=0;i<3;i++){
    int Ho = H*2;
    int oth = (cur == 0) ? 2 : 0;
    dim3 gconv((Ho+31)/32, Ho/8, 4);
    k_conv3x3_rt<<<gconv,256>>>(cur, up_w + i*64*64*9, up_b + i*64,
                                skipid[2-i], oth, nullptr, H, H, Ho, Ho, 1);
    cur = oth;
    H = Ho;
  }

  // final: fused (bilinear x4 resize + conv + silu) -> d_out
  dim3 gfin(8, 32, 4);
  k_conv3x3_rt<<<gfin,256>>>(cur, oc_w, oc_b, -1, -1, (float*)d_out,
                             64, 64, 256, 256, 1);
}